// round 7
// baseline (speedup 1.0000x reference)
#include <cuda_runtime.h>
#include <cuda_fp16.h>
#include <math.h>
#include <stdint.h>

// Problem constants
#define Bb 8
#define Nn 1024
#define Cc 768
#define Hh 12
#define Dd 64
#define Mtot (Bb*Nn)      // 8192
#define N1 (3*Cc)         // 2304

// Scratch (device globals: allocation-free rule)
__device__ float  g_q  [Bb*Hh*Nn*Dd];   // full q8 q (float, epilogue dot)
__device__ float  g_k  [Bb*Hh*Nn*Dd];
__device__ float  g_v  [Bb*Hh*Nn*Dd];
__device__ __half g_q4h[Bb*Hh*Nn*Dd];   // q4 q/k as fp16 (MMA operands)
__device__ __half g_k4h[Bb*Hh*Nn*Dd];
__device__ __half g_aoh[Bb*Hh*Nn*Dd];   // attention out, q8, fp16
__device__ __half g_xqh[Mtot*Cc];       // pre-quantized inputs (fp16 exact)
__device__ __half g_wqh[N1*Cc];
__device__ __half g_wph[Cc*Cc];

// quant forward: round-half-even fixed point (matches jnp.round)
__device__ __forceinline__ float q8f(float v){ return rintf(v*128.0f)*0.0078125f; }
__device__ __forceinline__ float q4f(float v){ return rintf(v*8.0f)*0.125f; }

// m16n8k16 fp16 MMA, fp32 accum.  All operands are n*2^-7 with |n|<2048
// -> fp16 exact; products/partials are small integers*2^-14 -> fp32 exact.
__device__ __forceinline__ void mma16(float* c, const uint32_t* a, uint32_t b0, uint32_t b1){
    asm volatile("mma.sync.aligned.m16n8k16.row.col.f32.f16.f16.f32 "
        "{%0,%1,%2,%3}, {%4,%5,%6,%7}, {%8,%9}, {%0,%1,%2,%3};\n"
        : "+f"(c[0]),"+f"(c[1]),"+f"(c[2]),"+f"(c[3])
        : "r"(a[0]),"r"(a[1]),"r"(a[2]),"r"(a[3]), "r"(b0),"r"(b1));
}
__device__ __forceinline__ uint32_t ldh2(const __half* p){ return *(const uint32_t*)p; }

__device__ __forceinline__ void cp16h(__half* smem_dst, const __half* gsrc){
    uint32_t s = (uint32_t)__cvta_generic_to_shared(smem_dst);
    asm volatile("cp.async.cg.shared.global [%0], [%1], 16;\n" :: "r"(s), "l"(gsrc));
}
#define CP_COMMIT() asm volatile("cp.async.commit_group;\n"::)
#define CP_WAIT1()  asm volatile("cp.async.wait_group 1;\n"::)
#define CP_WAIT0()  asm volatile("cp.async.wait_group 0;\n"::)

// ---------------------------------------------------------------------------
// Pre-quantize x, w_qkv, w_proj -> fp16 (q8 values are fp16-exact).
// ---------------------------------------------------------------------------
#define NX4 (Mtot*Cc/4)
#define NW4 (N1*Cc/4)
#define NP4 (Cc*Cc/4)
__global__ __launch_bounds__(256) void quant_prep(
        const float* __restrict__ X, const float* __restrict__ Wq,
        const float* __restrict__ Wp)
{
    int i = blockIdx.x*256 + threadIdx.x;
    const float* src; __half* dst;
    if(i < NX4){ src = X; dst = g_xqh; }
    else if(i < NX4+NW4){ src = Wq; dst = g_wqh; i -= NX4; }
    else { src = Wp; dst = g_wph; i -= NX4+NW4; }
    float4 v = ((const float4*)src)[i];
    __half2* d2 = (__half2*)dst;
    d2[2*i]   = __halves2half2(__float2half_rn(q8f(v.x)), __float2half_rn(q8f(v.y)));
    d2[2*i+1] = __halves2half2(__float2half_rn(q8f(v.z)), __float2half_rn(q8f(v.w)));
}

// ---------------------------------------------------------------------------
// GEMMs: 128x128 tile, K-chunk 32, 3-stage cp.async ring, ONE barrier/stage.
// Ordering per iter s: wait_group(1) [stage s arrived] -> __syncthreads
// [publish + all warps done reading slot (s+2)%3] -> prefetch stage s+2 into
// slot (s+2)%3 -> commit -> MMA on stage s.
// PROJ=0: qkv (A=g_xqh, B=g_wqh, q8/q4 scatter epilogue)
// PROJ=1: proj (A=g_aoh gathered per-head, B=g_wph, out+bias epilogue)
// ---------------------------------------------------------------------------
#define HS 40
#define STG (128*HS)
#define GEMM3_SMEM (6*STG*2)    // 3 stages x (A+B) x 2B = 61440

template<int PROJ>
__global__ __launch_bounds__(256,2) void gemm_h3(
        const float* __restrict__ bias, float* __restrict__ out)
{
    extern __shared__ __half hsm[];
    __half* Ah = hsm;            // [3][STG]
    __half* Bh = hsm + 3*STG;    // [3][STG]

    int m0 = blockIdx.y*128, n0 = blockIdx.x*128;
    int tid = threadIdx.x, lane = tid&31, warp = tid>>5;
    int g = lane>>2, tg = lane&3;
    int wm = warp>>2, wn = warp&3;
    int bidx  = m0>>10;
    int nbase = m0&1023;
    const __half* Abase = g_aoh + (size_t)bidx*(Hh*Nn*Dd);
    const __half* Wsrc  = PROJ ? g_wph : g_wqh;

    float acc[4][4][4];
    #pragma unroll
    for(int a=0;a<4;a++)
        #pragma unroll
        for(int b=0;b<4;b++)
            #pragma unroll
            for(int c=0;c<4;c++) acc[a][b][c]=0.f;

    int srow = tid>>2, sc8 = tid&3;          // 64 rows x 4 col-chunks, x2 rows

    // prefetch one 32-wide K stage
    auto stage = [&](int st){
        int slot = st - (st/3)*3;
        int k0 = st*32;
        int c  = k0 + sc8*8;
        #pragma unroll
        for(int r=0;r<2;r++){
            const __half* asrc;
            if(PROJ){
                int h = c>>6, dd = c&63;
                asrc = Abase + ((size_t)h*Nn + nbase + srow + r*64)*Dd + dd;
            } else {
                asrc = g_xqh + (size_t)(m0 + srow + r*64)*Cc + c;
            }
            cp16h(&Ah[slot*STG + (srow+r*64)*HS + sc8*8], asrc);
            cp16h(&Bh[slot*STG + (srow+r*64)*HS + sc8*8],
                  Wsrc + (size_t)(n0 + srow + r*64)*Cc + c);
        }
    };

    stage(0); CP_COMMIT();
    stage(1); CP_COMMIT();

    for(int s=0;s<24;s++){
        CP_WAIT1();
        __syncthreads();
        if(s+2<24) stage(s+2);
        CP_COMMIT();
        int slot = s - (s/3)*3;
        const __half* As_ = Ah + slot*STG;
        const __half* Bs_ = Bh + slot*STG;
        #pragma unroll
        for(int ks=0;ks<2;ks++){
            uint32_t af[4][4], bf[4][2];
            #pragma unroll
            for(int mt=0;mt<4;mt++){
                int base = (wm*64+mt*16+g)*HS + ks*16 + 2*tg;
                af[mt][0]=ldh2(&As_[base]);      af[mt][1]=ldh2(&As_[base+8*HS]);
                af[mt][2]=ldh2(&As_[base+8]);    af[mt][3]=ldh2(&As_[base+8*HS+8]);
            }
            #pragma unroll
            for(int nt=0;nt<4;nt++){
                int base = (wn*32+nt*8+g)*HS + ks*16 + 2*tg;
                bf[nt][0]=ldh2(&Bs_[base]); bf[nt][1]=ldh2(&Bs_[base+8]);
            }
            #pragma unroll
            for(int mt=0;mt<4;mt++)
                #pragma unroll
                for(int nt=0;nt<4;nt++)
                    mma16(acc[mt][nt], af[mt], bf[nt][0], bf[nt][1]);
        }
    }

    // epilogue
    #pragma unroll
    for(int mt=0;mt<4;mt++)
        #pragma unroll
        for(int nt=0;nt<4;nt++)
            #pragma unroll
            for(int i=0;i<4;i++){
                int mrow = m0 + wm*64 + mt*16 + g + ((i>=2)?8:0);
                int col  = n0 + wn*32 + nt*8 + 2*tg + (i&1);
                if(PROJ){
                    out[(size_t)mrow*Cc + col] = acc[mt][nt][i] + bias[col];
                } else {
                    int bb = mrow>>10, nrow = mrow&1023;
                    int t = col/Cc, rem = col - t*Cc;
                    int h = rem>>6, dd = rem&63;
                    float val = q8f(acc[mt][nt][i]);
                    size_t idx = (((size_t)(bb*Hh)+h)*Nn + nrow)*Dd + dd;
                    if(t==0){ g_q[idx]=val; g_q4h[idx]=__float2half_rn(q4f(val)); }
                    else if(t==1){ g_k[idx]=val; g_k4h[idx]=__float2half_rn(q4f(val)); }
                    else g_v[idx]=val;
                }
            }
}

// ---------------------------------------------------------------------------
// Attention v4: one-hot collapse, QT=128 queries/CTA, fp16 msb MMA,
// online (max,sum,argmax), tiny per-row epilogue.  (unchanged from R5)
// ---------------------------------------------------------------------------
#define AS 72
__global__ __launch_bounds__(512) void attn_v4()
{
    __shared__ __half qm[128*AS];
    __shared__ __half kt[2][64*AS];
    __shared__ float  red[2*128*4];

    int bh = blockIdx.y;
    int q0 = blockIdx.x*128;
    const __half* Q4 = g_q4h + (size_t)bh*(Nn*Dd);
    const __half* K4 = g_k4h + (size_t)bh*(Nn*Dd);
    const float*  Qp = g_q   + (size_t)bh*(Nn*Dd);
    const float*  Kp = g_k   + (size_t)bh*(Nn*Dd);
    const float*  Vp = g_v   + (size_t)bh*(Nn*Dd);
    __half*       Oph= g_aoh + (size_t)bh*(Nn*Dd);

    int tid = threadIdx.x, lane = tid&31, warp = tid>>5;
    int g = lane>>2, tg = lane&3;
    int wm = warp>>1, wn = warp&1;
    int r0 = wm*16 + g;

    { int row=tid>>3, c8=tid&7;
      cp16h(&kt[0][row*AS+c8*8], K4 + (size_t)row*Dd + c8*8); }
    #pragma unroll
    for(int r=0;r<2;r++){
        int idx=tid+r*512, row=idx>>3, c8=idx&7;
        cp16h(&qm[row*AS+c8*8], Q4 + (size_t)(q0+row)*Dd + c8*8);
    }
    CP_COMMIT();
    CP_WAIT0();
    __syncthreads();

    uint32_t am[4][4];
    #pragma unroll
    for(int ks=0;ks<4;ks++){
        int base = r0*AS + ks*16 + 2*tg;
        am[ks][0]=ldh2(&qm[base]);     am[ks][1]=ldh2(&qm[base+8*AS]);
        am[ks][2]=ldh2(&qm[base+8]);   am[ks][3]=ldh2(&qm[base+8*AS+8]);
    }

    float m0s=-1e30f, s0=0.f; int i0=0;
    float m1s=-1e30f, s1=0.f; int i1=0;
    for(int t=0;t<16;t++){
        if(t<15){
            int row=tid>>3, c8=tid&7;
            cp16h(&kt[(t+1)&1][row*AS+c8*8],
                  K4 + (size_t)((t+1)*64+row)*Dd + c8*8);
            CP_COMMIT();
            CP_WAIT1();
        } else CP_WAIT0();
        __syncthreads();
        const __half* kb = kt[t&1];

        float accM[4][4];
        #pragma unroll
        for(int nt=0;nt<4;nt++)
            #pragma unroll
            for(int j=0;j<4;j++) accM[nt][j]=0.f;
        #pragma unroll
        for(int ks=0;ks<4;ks++){
            uint32_t bf[4][2];
            #pragma unroll
            for(int nt=0;nt<4;nt++){
                int base = (wn*32+nt*8+g)*AS + ks*16 + 2*tg;
                bf[nt][0]=ldh2(&kb[base]); bf[nt][1]=ldh2(&kb[base+8]);
            }
            #pragma unroll
            for(int nt=0;nt<4;nt++)
                mma16(accM[nt], am[ks], bf[nt][0], bf[nt][1]);
        }

        int cbase = t*64 + wn*32 + 2*tg;
        {   float tv[8]; int im=cbase; float vm=-1e30f;
            #pragma unroll
            for(int nt=0;nt<4;nt++){ tv[nt*2]=accM[nt][0]*0.125f; tv[nt*2+1]=accM[nt][1]*0.125f; }
            #pragma unroll
            for(int u=0;u<8;u++){
                int c = cbase + (u>>1)*8 + (u&1);
                if(tv[u]>vm){ vm=tv[u]; im=c; }
            }
            float nm = fmaxf(m0s, vm);
            float sadd=0.f;
            #pragma unroll
            for(int u=0;u<8;u++) sadd += __expf(tv[u]-nm);
            s0 = s0*__expf(m0s-nm) + sadd;
            if(vm > m0s) i0 = im;
            m0s = nm;
        }
        {   float tv[8]; int im=cbase; float vm=-1e30f;
            #pragma unroll
            for(int nt=0;nt<4;nt++){ tv[nt*2]=accM[nt][2]*0.125f; tv[nt*2+1]=accM[nt][3]*0.125f; }
            #pragma unroll
            for(int u=0;u<8;u++){
                int c = cbase + (u>>1)*8 + (u&1);
                if(tv[u]>vm){ vm=tv[u]; im=c; }
            }
            float nm = fmaxf(m1s, vm);
            float sadd=0.f;
            #pragma unroll
            for(int u=0;u<8;u++) sadd += __expf(tv[u]-nm);
            s1 = s1*__expf(m1s-nm) + sadd;
            if(vm > m1s) i1 = im;
            m1s = nm;
        }
        __syncthreads();
    }

    #pragma unroll
    for(int off=1; off<4; off<<=1){
        float om=__shfl_xor_sync(0xffffffffu,m0s,off);
        float os=__shfl_xor_sync(0xffffffffu,s0,off);
        int   oi=__shfl_xor_sync(0xffffffffu,i0,off);
        float nm=fmaxf(m0s,om);
        s0 = s0*__expf(m0s-nm)+os*__expf(om-nm);
        if(om>m0s) i0=oi;
        m0s=nm;
        om=__shfl_xor_sync(0xffffffffu,m1s,off);
        os=__shfl_xor_sync(0xffffffffu,s1,off);
        oi=__shfl_xor_sync(0xffffffffu,i1,off);
        nm=fmaxf(m1s,om);
        s1 = s1*__expf(m1s-nm)+os*__expf(om-nm);
        if(om>m1s) i1=oi;
        m1s=nm;
    }
    if(tg==0){
        int b0=(wn*128 + r0)*4;
        red[b0]=m0s; red[b0+1]=s0; red[b0+2]=(float)i0;
        int b1=(wn*128 + r0+8)*4;
        red[b1]=m1s; red[b1+1]=s1; red[b1+2]=(float)i1;
    }
    __syncthreads();

    for(int rr=warp; rr<128; rr+=16){
        float ma=red[rr*4],       sa=red[rr*4+1];       int ia=(int)red[rr*4+2];
        float mb=red[(128+rr)*4], sb=red[(128+rr)*4+1]; int ib=(int)red[(128+rr)*4+2];
        float nm=fmaxf(ma,mb);
        float s = sa*__expf(ma-nm) + sb*__expf(mb-nm);
        int ix = (mb>ma)? ib : ia;
        int grow = q0 + rr;
        __half* orow = Oph + (size_t)grow*Dd;
        if(s*0.99f < 1.0f){
            float2 qv = *(const float2*)(Qp + (size_t)grow*Dd + 2*lane);
            float2 kv = *(const float2*)(Kp + (size_t)ix*Dd + 2*lane);
            float part = qv.x*kv.x + qv.y*kv.y;
            #pragma unroll
            for(int off=16; off; off>>=1)
                part += __shfl_xor_sync(0xffffffffu, part, off);
            float L  = part*0.125f;
            float mm = fmaxf(L, 0.f);
            float eL = __expf(L-mm);
            float pq = q8f(eL / (eL + 1023.0f*__expf(-mm)));
            float2 vv = *(const float2*)(Vp + (size_t)ix*Dd + 2*lane);
            orow[2*lane]   = __float2half_rn(q8f(pq*vv.x));
            orow[2*lane+1] = __float2half_rn(q8f(pq*vv.y));
        } else {
            orow[2*lane]   = __float2half_rn(0.f);
            orow[2*lane+1] = __float2half_rn(0.f);
        }
    }
}

// ---------------------------------------------------------------------------
extern "C" void kernel_launch(void* const* d_in, const int* in_sizes, int n_in,
                              void* d_out, int out_size)
{
    const float* x      = (const float*)d_in[0];
    const float* w_qkv  = (const float*)d_in[1];
    const float* w_proj = (const float*)d_in[2];
    const float* b_proj = (const float*)d_in[3];
    float* out = (float*)d_out;

    cudaFuncSetAttribute(gemm_h3<0>, cudaFuncAttributeMaxDynamicSharedMemorySize, GEMM3_SMEM);
    cudaFuncSetAttribute(gemm_h3<1>, cudaFuncAttributeMaxDynamicSharedMemorySize, GEMM3_SMEM);

    quant_prep<<<(NX4+NW4+NP4)/256, 256>>>(x, w_qkv, w_proj);
    gemm_h3<0><<<dim3(N1/128, Mtot/128), 256, GEMM3_SMEM>>>(nullptr, nullptr);
    attn_v4<<<dim3(Nn/128, Bb*Hh), 512>>>();
    gemm_h3<1><<<dim3(Cc/128, Mtot/128), 256, GEMM3_SMEM>>>(b_proj, out);
}

// round 8
// speedup vs baseline: 1.0938x; 1.0938x over previous
#include <cuda_runtime.h>
#include <cuda_fp16.h>
#include <math.h>
#include <stdint.h>

// Problem constants
#define Bb 8
#define Nn 1024
#define Cc 768
#define Hh 12
#define Dd 64
#define Mtot (Bb*Nn)      // 8192
#define N1 (3*Cc)         // 2304

// Scratch (device globals: allocation-free rule)
__device__ float  g_q  [Bb*Hh*Nn*Dd];
__device__ float  g_k  [Bb*Hh*Nn*Dd];
__device__ float  g_v  [Bb*Hh*Nn*Dd];
__device__ __half g_q4h[Bb*Hh*Nn*Dd];
__device__ __half g_k4h[Bb*Hh*Nn*Dd];
__device__ __half g_aoh[Bb*Hh*Nn*Dd];
__device__ __half g_xqh[Mtot*Cc];
__device__ __half g_wqh[N1*Cc];
__device__ __half g_wph[Cc*Cc];

__device__ __forceinline__ float q8f(float v){ return rintf(v*128.0f)*0.0078125f; }
__device__ __forceinline__ float q4f(float v){ return rintf(v*8.0f)*0.125f; }

__device__ __forceinline__ void mma16(float* c, const uint32_t* a, uint32_t b0, uint32_t b1){
    asm volatile("mma.sync.aligned.m16n8k16.row.col.f32.f16.f16.f32 "
        "{%0,%1,%2,%3}, {%4,%5,%6,%7}, {%8,%9}, {%0,%1,%2,%3};\n"
        : "+f"(c[0]),"+f"(c[1]),"+f"(c[2]),"+f"(c[3])
        : "r"(a[0]),"r"(a[1]),"r"(a[2]),"r"(a[3]), "r"(b0),"r"(b1));
}
__device__ __forceinline__ uint32_t ldh2(const __half* p){ return *(const uint32_t*)p; }

__device__ __forceinline__ uint32_t smem_u32(const void* p){
    uint32_t a;
    asm("{ .reg .u64 t; cvta.to.shared.u64 t, %1; cvt.u32.u64 %0, t; }" : "=r"(a) : "l"(p));
    return a;
}
#define LDSM4(r, addr) \
    asm volatile("ldmatrix.sync.aligned.m8n8.x4.shared.b16 {%0,%1,%2,%3}, [%4];" \
        : "=r"((r)[0]),"=r"((r)[1]),"=r"((r)[2]),"=r"((r)[3]) : "r"(addr))

__device__ __forceinline__ void cp16h(__half* smem_dst, const __half* gsrc){
    uint32_t s = (uint32_t)__cvta_generic_to_shared(smem_dst);
    asm volatile("cp.async.cg.shared.global [%0], [%1], 16;\n" :: "r"(s), "l"(gsrc));
}
#define CP_COMMIT() asm volatile("cp.async.commit_group;\n"::)
#define CP_WAIT1()  asm volatile("cp.async.wait_group 1;\n"::)
#define CP_WAIT0()  asm volatile("cp.async.wait_group 0;\n"::)

// ---------------------------------------------------------------------------
// Pre-quantize x, w_qkv, w_proj -> fp16 (q8 values are fp16-exact).
// ---------------------------------------------------------------------------
#define NX4 (Mtot*Cc/4)
#define NW4 (N1*Cc/4)
#define NP4 (Cc*Cc/4)
__global__ __launch_bounds__(256) void quant_prep(
        const float* __restrict__ X, const float* __restrict__ Wq,
        const float* __restrict__ Wp)
{
    int i = blockIdx.x*256 + threadIdx.x;
    const float* src; __half* dst;
    if(i < NX4){ src = X; dst = g_xqh; }
    else if(i < NX4+NW4){ src = Wq; dst = g_wqh; i -= NX4; }
    else { src = Wp; dst = g_wph; i -= NX4+NW4; }
    float4 v = ((const float4*)src)[i];
    __half2* d2 = (__half2*)dst;
    d2[2*i]   = __halves2half2(__float2half_rn(q8f(v.x)), __float2half_rn(q8f(v.y)));
    d2[2*i+1] = __halves2half2(__float2half_rn(q8f(v.z)), __float2half_rn(q8f(v.w)));
}

// ---------------------------------------------------------------------------
// GEMMs: 128x128 tile, K-chunk 32, 3-stage cp.async ring, ldmatrix fragments.
// PROJ=0: qkv (A=g_xqh, B=g_wqh, q8/q4 scatter epilogue)
// PROJ=1: proj (A=g_aoh gathered per-head, B=g_wph, out+bias epilogue)
// ---------------------------------------------------------------------------
#define HS 40
#define STG (128*HS)          // halfs per stage per matrix
#define STGB (STG*2)          // bytes
#define GEMM3_SMEM (6*STG*2)  // 61440 B

template<int PROJ>
__global__ __launch_bounds__(256,2) void gemm_h3(
        const float* __restrict__ bias, float* __restrict__ out)
{
    extern __shared__ __half hsm[];
    __half* Ah = hsm;            // [3][STG]
    __half* Bh = hsm + 3*STG;    // [3][STG]
    uint32_t sbA = smem_u32(Ah), sbB = smem_u32(Bh);

    int m0 = blockIdx.y*128, n0 = blockIdx.x*128;
    int tid = threadIdx.x, lane = tid&31, warp = tid>>5;
    int g = lane>>2, tg = lane&3;
    int wm = warp>>2, wn = warp&3;
    int bidx  = m0>>10;
    int nbase = m0&1023;
    const __half* Abase = g_aoh + (size_t)bidx*(Hh*Nn*Dd);
    const __half* Wsrc  = PROJ ? g_wph : g_wqh;

    float acc[4][4][4];
    #pragma unroll
    for(int a=0;a<4;a++)
        #pragma unroll
        for(int b=0;b<4;b++)
            #pragma unroll
            for(int c=0;c<4;c++) acc[a][b][c]=0.f;

    // ldmatrix per-thread element offsets (in halfs), before ks/slot shifts
    uint32_t aoff[4], boff[2];
    #pragma unroll
    for(int mt=0;mt<4;mt++)
        aoff[mt] = (uint32_t)((wm*64 + mt*16 + (lane&15))*HS + (lane>>4)*8);
    #pragma unroll
    for(int p=0;p<2;p++)
        boff[p] = (uint32_t)((wn*32 + p*16 + (lane>>4)*8 + (lane&7))*HS
                             + ((lane>>3)&1)*8);

    int srow = tid>>2, sc8 = tid&3;

    auto stage = [&](int st){
        int slot = st - (st/3)*3;
        int k0 = st*32;
        int c  = k0 + sc8*8;
        #pragma unroll
        for(int r=0;r<2;r++){
            const __half* asrc;
            if(PROJ){
                int h = c>>6, dd = c&63;
                asrc = Abase + ((size_t)h*Nn + nbase + srow + r*64)*Dd + dd;
            } else {
                asrc = g_xqh + (size_t)(m0 + srow + r*64)*Cc + c;
            }
            cp16h(&Ah[slot*STG + (srow+r*64)*HS + sc8*8], asrc);
            cp16h(&Bh[slot*STG + (srow+r*64)*HS + sc8*8],
                  Wsrc + (size_t)(n0 + srow + r*64)*Cc + c);
        }
    };

    stage(0); CP_COMMIT();
    stage(1); CP_COMMIT();

    for(int s=0;s<24;s++){
        CP_WAIT1();
        __syncthreads();
        if(s+2<24) stage(s+2);
        CP_COMMIT();
        int slot = s - (s/3)*3;
        uint32_t baseA = sbA + slot*STGB;
        uint32_t baseB = sbB + slot*STGB;
        #pragma unroll
        for(int ks=0;ks<2;ks++){
            uint32_t af[4][4], bf[2][4];
            #pragma unroll
            for(int mt=0;mt<4;mt++)
                LDSM4(af[mt], baseA + (aoff[mt] + ks*16)*2);
            #pragma unroll
            for(int p=0;p<2;p++)
                LDSM4(bf[p], baseB + (boff[p] + ks*16)*2);
            #pragma unroll
            for(int mt=0;mt<4;mt++)
                #pragma unroll
                for(int p=0;p<2;p++){
                    mma16(acc[mt][2*p  ], af[mt], bf[p][0], bf[p][1]);
                    mma16(acc[mt][2*p+1], af[mt], bf[p][2], bf[p][3]);
                }
        }
    }

    // epilogue
    #pragma unroll
    for(int mt=0;mt<4;mt++)
        #pragma unroll
        for(int nt=0;nt<4;nt++)
            #pragma unroll
            for(int i=0;i<4;i++){
                int mrow = m0 + wm*64 + mt*16 + g + ((i>=2)?8:0);
                int col  = n0 + wn*32 + nt*8 + 2*tg + (i&1);
                if(PROJ){
                    out[(size_t)mrow*Cc + col] = acc[mt][nt][i] + bias[col];
                } else {
                    int bb = mrow>>10, nrow = mrow&1023;
                    int t = col/Cc, rem = col - t*Cc;
                    int h = rem>>6, dd = rem&63;
                    float val = q8f(acc[mt][nt][i]);
                    size_t idx = (((size_t)(bb*Hh)+h)*Nn + nrow)*Dd + dd;
                    if(t==0){ g_q[idx]=val; g_q4h[idx]=__float2half_rn(q4f(val)); }
                    else if(t==1){ g_k[idx]=val; g_k4h[idx]=__float2half_rn(q4f(val)); }
                    else g_v[idx]=val;
                }
            }
}

// ---------------------------------------------------------------------------
// Attention v4: one-hot collapse, QT=128 queries/CTA, fp16 msb MMA,
// online (max,sum,argmax), tiny per-row epilogue.  (unchanged)
// ---------------------------------------------------------------------------
#define AS 72
__global__ __launch_bounds__(512) void attn_v4()
{
    __shared__ __half qm[128*AS];
    __shared__ __half kt[2][64*AS];
    __shared__ float  red[2*128*4];

    int bh = blockIdx.y;
    int q0 = blockIdx.x*128;
    const __half* Q4 = g_q4h + (size_t)bh*(Nn*Dd);
    const __half* K4 = g_k4h + (size_t)bh*(Nn*Dd);
    const float*  Qp = g_q   + (size_t)bh*(Nn*Dd);
    const float*  Kp = g_k   + (size_t)bh*(Nn*Dd);
    const float*  Vp = g_v   + (size_t)bh*(Nn*Dd);
    __half*       Oph= g_aoh + (size_t)bh*(Nn*Dd);

    int tid = threadIdx.x, lane = tid&31, warp = tid>>5;
    int g = lane>>2, tg = lane&3;
    int wm = warp>>1, wn = warp&1;
    int r0 = wm*16 + g;

    { int row=tid>>3, c8=tid&7;
      cp16h(&kt[0][row*AS+c8*8], K4 + (size_t)row*Dd + c8*8); }
    #pragma unroll
    for(int r=0;r<2;r++){
        int idx=tid+r*512, row=idx>>3, c8=idx&7;
        cp16h(&qm[row*AS+c8*8], Q4 + (size_t)(q0+row)*Dd + c8*8);
    }
    CP_COMMIT();
    CP_WAIT0();
    __syncthreads();

    uint32_t am[4][4];
    #pragma unroll
    for(int ks=0;ks<4;ks++){
        int base = r0*AS + ks*16 + 2*tg;
        am[ks][0]=ldh2(&qm[base]);     am[ks][1]=ldh2(&qm[base+8*AS]);
        am[ks][2]=ldh2(&qm[base+8]);   am[ks][3]=ldh2(&qm[base+8*AS+8]);
    }

    float m0s=-1e30f, s0=0.f; int i0=0;
    float m1s=-1e30f, s1=0.f; int i1=0;
    for(int t=0;t<16;t++){
        if(t<15){
            int row=tid>>3, c8=tid&7;
            cp16h(&kt[(t+1)&1][row*AS+c8*8],
                  K4 + (size_t)((t+1)*64+row)*Dd + c8*8);
            CP_COMMIT();
            CP_WAIT1();
        } else CP_WAIT0();
        __syncthreads();
        const __half* kb = kt[t&1];

        float accM[4][4];
        #pragma unroll
        for(int nt=0;nt<4;nt++)
            #pragma unroll
            for(int j=0;j<4;j++) accM[nt][j]=0.f;
        #pragma unroll
        for(int ks=0;ks<4;ks++){
            uint32_t bf[4][2];
            #pragma unroll
            for(int nt=0;nt<4;nt++){
                int base = (wn*32+nt*8+g)*AS + ks*16 + 2*tg;
                bf[nt][0]=ldh2(&kb[base]); bf[nt][1]=ldh2(&kb[base+8]);
            }
            #pragma unroll
            for(int nt=0;nt<4;nt++)
                mma16(accM[nt], am[ks], bf[nt][0], bf[nt][1]);
        }

        int cbase = t*64 + wn*32 + 2*tg;
        {   float tv[8]; int im=cbase; float vm=-1e30f;
            #pragma unroll
            for(int nt=0;nt<4;nt++){ tv[nt*2]=accM[nt][0]*0.125f; tv[nt*2+1]=accM[nt][1]*0.125f; }
            #pragma unroll
            for(int u=0;u<8;u++){
                int c = cbase + (u>>1)*8 + (u&1);
                if(tv[u]>vm){ vm=tv[u]; im=c; }
            }
            float nm = fmaxf(m0s, vm);
            float sadd=0.f;
            #pragma unroll
            for(int u=0;u<8;u++) sadd += __expf(tv[u]-nm);
            s0 = s0*__expf(m0s-nm) + sadd;
            if(vm > m0s) i0 = im;
            m0s = nm;
        }
        {   float tv[8]; int im=cbase; float vm=-1e30f;
            #pragma unroll
            for(int nt=0;nt<4;nt++){ tv[nt*2]=accM[nt][2]*0.125f; tv[nt*2+1]=accM[nt][3]*0.125f; }
            #pragma unroll
            for(int u=0;u<8;u++){
                int c = cbase + (u>>1)*8 + (u&1);
                if(tv[u]>vm){ vm=tv[u]; im=c; }
            }
            float nm = fmaxf(m1s, vm);
            float sadd=0.f;
            #pragma unroll
            for(int u=0;u<8;u++) sadd += __expf(tv[u]-nm);
            s1 = s1*__expf(m1s-nm) + sadd;
            if(vm > m1s) i1 = im;
            m1s = nm;
        }
        __syncthreads();
    }

    #pragma unroll
    for(int off=1; off<4; off<<=1){
        float om=__shfl_xor_sync(0xffffffffu,m0s,off);
        float os=__shfl_xor_sync(0xffffffffu,s0,off);
        int   oi=__shfl_xor_sync(0xffffffffu,i0,off);
        float nm=fmaxf(m0s,om);
        s0 = s0*__expf(m0s-nm)+os*__expf(om-nm);
        if(om>m0s) i0=oi;
        m0s=nm;
        om=__shfl_xor_sync(0xffffffffu,m1s,off);
        os=__shfl_xor_sync(0xffffffffu,s1,off);
        oi=__shfl_xor_sync(0xffffffffu,i1,off);
        nm=fmaxf(m1s,om);
        s1 = s1*__expf(m1s-nm)+os*__expf(om-nm);
        if(om>m1s) i1=oi;
        m1s=nm;
    }
    if(tg==0){
        int b0=(wn*128 + r0)*4;
        red[b0]=m0s; red[b0+1]=s0; red[b0+2]=(float)i0;
        int b1=(wn*128 + r0+8)*4;
        red[b1]=m1s; red[b1+1]=s1; red[b1+2]=(float)i1;
    }
    __syncthreads();

    for(int rr=warp; rr<128; rr+=16){
        float ma=red[rr*4],       sa=red[rr*4+1];       int ia=(int)red[rr*4+2];
        float mb=red[(128+rr)*4], sb=red[(128+rr)*4+1]; int ib=(int)red[(128+rr)*4+2];
        float nm=fmaxf(ma,mb);
        float s = sa*__expf(ma-nm) + sb*__expf(mb-nm);
        int ix = (mb>ma)? ib : ia;
        int grow = q0 + rr;
        __half* orow = Oph + (size_t)grow*Dd;
        if(s*0.99f < 1.0f){
            float2 qv = *(const float2*)(Qp + (size_t)grow*Dd + 2*lane);
            float2 kv = *(const float2*)(Kp + (size_t)ix*Dd + 2*lane);
            float part = qv.x*kv.x + qv.y*kv.y;
            #pragma unroll
            for(int off=16; off; off>>=1)
                part += __shfl_xor_sync(0xffffffffu, part, off);
            float L  = part*0.125f;
            float mm = fmaxf(L, 0.f);
            float eL = __expf(L-mm);
            float pq = q8f(eL / (eL + 1023.0f*__expf(-mm)));
            float2 vv = *(const float2*)(Vp + (size_t)ix*Dd + 2*lane);
            orow[2*lane]   = __float2half_rn(q8f(pq*vv.x));
            orow[2*lane+1] = __float2half_rn(q8f(pq*vv.y));
        } else {
            orow[2*lane]   = __float2half_rn(0.f);
            orow[2*lane+1] = __float2half_rn(0.f);
        }
    }
}

// ---------------------------------------------------------------------------
extern "C" void kernel_launch(void* const* d_in, const int* in_sizes, int n_in,
                              void* d_out, int out_size)
{
    const float* x      = (const float*)d_in[0];
    const float* w_qkv  = (const float*)d_in[1];
    const float* w_proj = (const float*)d_in[2];
    const float* b_proj = (const float*)d_in[3];
    float* out = (float*)d_out;

    cudaFuncSetAttribute(gemm_h3<0>, cudaFuncAttributeMaxDynamicSharedMemorySize, GEMM3_SMEM);
    cudaFuncSetAttribute(gemm_h3<1>, cudaFuncAttributeMaxDynamicSharedMemorySize, GEMM3_SMEM);

    quant_prep<<<(NX4+NW4+NP4)/256, 256>>>(x, w_qkv, w_proj);
    gemm_h3<0><<<dim3(N1/128, Mtot/128), 256, GEMM3_SMEM>>>(nullptr, nullptr);
    attn_v4<<<dim3(Nn/128, Bb*Hh), 512>>>();
    gemm_h3<1><<<dim3(Cc/128, Mtot/128), 256, GEMM3_SMEM>>>(b_proj, out);
}